// round 3
// baseline (speedup 1.0000x reference)
#include <cuda_runtime.h>
#include <cuda_bf16.h>
#include <stdint.h>

// Problem constants
#define MAXN 40000
#define MAXE 640000
#define NG   64
#define F    128   // feature dim (F_IN == H == 128)

// ---------------- device scratch (no allocations allowed) ----------------
__device__ float g_bufA[(size_t)MAXN * F];   // GEMM output / aggregation input
__device__ float g_bufB[(size_t)MAXN * F];   // aggregation output / next GEMM input
__device__ int   g_deg[MAXN];
__device__ float g_dis[MAXN];
__device__ int   g_rowptr[MAXN + 1];
__device__ int   g_tmp[MAXN];
__device__ int   g_csr[MAXE + MAXN];
__device__ float g_gsum[NG];
__device__ float g_gcnt[NG];

// ---------------- init: deg=1 (self loop), tmp=0, graph accumulators=0 ----
__global__ void init_kernel(int n) {
    int i = blockIdx.x * blockDim.x + threadIdx.x;
    if (i < n) { g_deg[i] = 1; g_tmp[i] = 0; }
    if (i < NG) { g_gsum[i] = 0.f; g_gcnt[i] = 0.f; }
}

// ---------------- in-degree histogram over edge targets -------------------
__global__ void count_kernel(const int* __restrict__ col, int E, int n) {
    int e = blockIdx.x * blockDim.x + threadIdx.x;
    if (e < E) {
        unsigned c = (unsigned)col[e];
        if (c < (unsigned)n) atomicAdd(&g_deg[c], 1);
    }
}

// ---------------- dis = rsqrt(deg) ----------------------------------------
__global__ void dis_kernel(int n) {
    int i = blockIdx.x * blockDim.x + threadIdx.x;
    if (i < n) g_dis[i] = rsqrtf((float)g_deg[i]);
}

// ---------------- single-block exclusive scan of deg -> rowptr ------------
__global__ void scan_kernel(int n) {
    __shared__ int sh_ws[32];
    __shared__ int sh_carry;
    int tid = threadIdx.x, lane = tid & 31, wid = tid >> 5;
    if (tid == 0) sh_carry = 0;
    __syncthreads();
    for (int base = 0; base < n; base += 1024) {
        int i = base + tid;
        int v = (i < n) ? g_deg[i] : 0;
        int x = v;
#pragma unroll
        for (int o = 1; o < 32; o <<= 1) {
            int y = __shfl_up_sync(0xffffffffu, x, o);
            if (lane >= o) x += y;
        }
        if (lane == 31) sh_ws[wid] = x;
        __syncthreads();
        if (wid == 0) {
            int w = sh_ws[lane];
#pragma unroll
            for (int o = 1; o < 32; o <<= 1) {
                int y = __shfl_up_sync(0xffffffffu, w, o);
                if (lane >= o) w += y;
            }
            sh_ws[lane] = w;
        }
        __syncthreads();
        int warp_off = (wid > 0) ? sh_ws[wid - 1] : 0;
        if (i < n) g_rowptr[i] = sh_carry + warp_off + x - v;
        int total = sh_ws[31];
        __syncthreads();
        if (tid == 0) sh_carry += total;
        __syncthreads();
    }
    if (threadIdx.x == 0) g_rowptr[n] = sh_carry;
}

// ---------------- scatter edges (+self loops) into CSR by destination -----
__global__ void scatter_kernel(const int* __restrict__ row,
                               const int* __restrict__ col,
                               int E, int n) {
    int idx = blockIdx.x * blockDim.x + threadIdx.x;
    int total = E + n;
    if (idx >= total) return;
    unsigned d, s;
    if (idx < E) { d = (unsigned)col[idx]; s = (unsigned)row[idx]; }
    else         { d = (unsigned)(idx - E); s = d; }
    if (d >= (unsigned)n || s >= (unsigned)n) return;
    int p = g_rowptr[d] + atomicAdd(&g_tmp[d], 1);
    g_csr[p] = (int)s;
}

// ---------------- SGEMM: g_bufA[M,128] = A @ W[128,128] + bias ------------
// useBuf=0: A = xExt (first layer). useBuf=1: A = g_bufB.
__global__ __launch_bounds__(256)
void gemm_bias_kernel(const float* __restrict__ xExt, int useBuf,
                      const float* __restrict__ W,
                      const float* __restrict__ bias, int M) {
    const float* __restrict__ A = useBuf ? (const float*)g_bufB : xExt;
    float* __restrict__ C = g_bufA;

    __shared__ float As[16][128];  // [k][m]
    __shared__ float Bs[16][128];  // [k][n]
    const int t = threadIdx.x;
    const int blockM = blockIdx.x * 128;
    const int tRow = (t >> 4) * 8;   // 0..120
    const int tCol = (t & 15) * 8;   // 0..120

    float acc[8][8];
#pragma unroll
    for (int i = 0; i < 8; i++)
#pragma unroll
        for (int j = 0; j < 8; j++) acc[i][j] = 0.f;

    for (int k0 = 0; k0 < 128; k0 += 16) {
        // load A tile (128 rows x 16 cols), transposed into As[k][m]
#pragma unroll
        for (int l = 0; l < 2; l++) {
            int f = t + l * 256;            // 0..511
            int rl = f >> 2;                // row local 0..127
            int seg = (f & 3) * 4;          // col seg 0,4,8,12
            int grow = blockM + rl;
            float4 v = make_float4(0.f, 0.f, 0.f, 0.f);
            if (grow < M)
                v = *(const float4*)(A + (size_t)grow * 128 + k0 + seg);
            As[seg + 0][rl] = v.x;
            As[seg + 1][rl] = v.y;
            As[seg + 2][rl] = v.z;
            As[seg + 3][rl] = v.w;
        }
        // load W tile (16 rows x 128 cols), direct
#pragma unroll
        for (int l = 0; l < 2; l++) {
            int f = t + l * 256;            // 0..511
            int kr = f >> 5;                // 0..15
            int cs = (f & 31) * 4;
            float4 v = *(const float4*)(W + (size_t)(k0 + kr) * 128 + cs);
            *(float4*)(&Bs[kr][cs]) = v;
        }
        __syncthreads();
#pragma unroll
        for (int kk = 0; kk < 16; kk++) {
            float ra[8], rb[8];
#pragma unroll
            for (int i = 0; i < 8; i++) ra[i] = As[kk][tRow + i];
#pragma unroll
            for (int j = 0; j < 8; j++) rb[j] = Bs[kk][tCol + j];
#pragma unroll
            for (int i = 0; i < 8; i++)
#pragma unroll
                for (int j = 0; j < 8; j++)
                    acc[i][j] = fmaf(ra[i], rb[j], acc[i][j]);
        }
        __syncthreads();
    }
    // epilogue: add bias, store
    float b0[8];
#pragma unroll
    for (int j = 0; j < 8; j++) b0[j] = bias[tCol + j];
#pragma unroll
    for (int i = 0; i < 8; i++) {
        int grow = blockM + tRow + i;
        if (grow < M) {
            float4 v0, v1;
            v0.x = acc[i][0] + b0[0]; v0.y = acc[i][1] + b0[1];
            v0.z = acc[i][2] + b0[2]; v0.w = acc[i][3] + b0[3];
            v1.x = acc[i][4] + b0[4]; v1.y = acc[i][5] + b0[5];
            v1.z = acc[i][6] + b0[6]; v1.w = acc[i][7] + b0[7];
            float* cp = C + (size_t)grow * 128 + tCol;
            *(float4*)(cp)     = v0;
            *(float4*)(cp + 4) = v1;
        }
    }
}

// ------ CSR gather aggregation: g_bufB = relu(dis[d]*sum dis[s]*g_bufA[s]) -
__global__ __launch_bounds__(256)
void aggregate_kernel(int n) {
    int node = blockIdx.x * 8 + (threadIdx.x >> 5);
    if (node >= n) return;
    int lane = threadIdx.x & 31;
    const float* __restrict__ h = g_bufA;
    int s = g_rowptr[node];
    int e = g_rowptr[node + 1];
    float4 acc = make_float4(0.f, 0.f, 0.f, 0.f);
    for (int p = s; p < e; p++) {
        int src = g_csr[p];
        float w = g_dis[src];
        float4 v = *(const float4*)(h + (size_t)src * 128 + lane * 4);
        acc.x = fmaf(w, v.x, acc.x);
        acc.y = fmaf(w, v.y, acc.y);
        acc.z = fmaf(w, v.z, acc.z);
        acc.w = fmaf(w, v.w, acc.w);
    }
    float dd = g_dis[node];
    acc.x = fmaxf(acc.x * dd, 0.f);
    acc.y = fmaxf(acc.y * dd, 0.f);
    acc.z = fmaxf(acc.z * dd, 0.f);
    acc.w = fmaxf(acc.w * dd, 0.f);
    *(float4*)(g_bufB + (size_t)node * 128 + lane * 4) = acc;
}

// ---------------- pooling: per-node dot with Wl, segment-sum by graph -----
__global__ __launch_bounds__(256)
void pool_kernel(const int* __restrict__ batch,
                 const float* __restrict__ Wl, int n) {
    int node = blockIdx.x * 8 + (threadIdx.x >> 5);
    if (node >= n) return;
    int lane = threadIdx.x & 31;
    float4 w = *(const float4*)(Wl + lane * 4);
    float4 v = *(const float4*)(g_bufB + (size_t)node * 128 + lane * 4);
    float sv = v.x * w.x + v.y * w.y + v.z * w.z + v.w * w.w;
#pragma unroll
    for (int o = 16; o > 0; o >>= 1) sv += __shfl_xor_sync(0xffffffffu, sv, o);
    if (lane == 0) {
        unsigned b = (unsigned)batch[node];
        if (b < NG) {
            atomicAdd(&g_gsum[b], sv);
            atomicAdd(&g_gcnt[b], 1.0f);
        }
    }
}

__global__ void final_kernel(float* __restrict__ out, const float* __restrict__ bl) {
    int g = threadIdx.x;
    if (g < NG) out[g] = g_gsum[g] / fmaxf(g_gcnt[g], 1.0f) + bl[0];
}

// --------------------------------------------------------------------------
extern "C" void kernel_launch(void* const* d_in, const int* in_sizes, int n_in,
                              void* d_out, int out_size) {
    // Expected order: x, edge_index, batch, [dropout_rate], W1,b1,W2,b2,W3,b3,Wl,bl
    const float* x     = (const float*)d_in[0];
    const int*   eidx  = (const int*)d_in[1];    // int32 (JAX default, x64 disabled)
    const int*   batch = (const int*)d_in[2];

    // Detect whether dropout_rate scalar occupies slot 3 (size 1/tiny) or the
    // weights start there (W1 has 16384 elements).
    int wbase = (in_sizes[3] < 128) ? 4 : 3;
    const float* W1 = (const float*)d_in[wbase + 0];
    const float* b1 = (const float*)d_in[wbase + 1];
    const float* W2 = (const float*)d_in[wbase + 2];
    const float* b2 = (const float*)d_in[wbase + 3];
    const float* W3 = (const float*)d_in[wbase + 4];
    const float* b3 = (const float*)d_in[wbase + 5];
    const float* Wl = (const float*)d_in[wbase + 6];
    const float* bl = (const float*)d_in[wbase + 7];
    float* out = (float*)d_out;

    const int N = in_sizes[0] / F;          // 40000
    const int E = in_sizes[1] / 2;          // 640000
    const int* erow = eidx;                 // sources
    const int* ecol = eidx + E;             // targets

    const int T = 256;
    // 1) graph preprocessing -> CSR by destination
    init_kernel<<<(N + T - 1) / T, T>>>(N);
    count_kernel<<<(E + T - 1) / T, T>>>(ecol, E, N);
    dis_kernel<<<(N + T - 1) / T, T>>>(N);
    scan_kernel<<<1, 1024>>>(N);
    scatter_kernel<<<(E + N + T - 1) / T, T>>>(erow, ecol, E, N);

    const int gemmBlocks = (N + 127) / 128;
    const int aggBlocks  = (N + 7) / 8;

    // layer 1
    gemm_bias_kernel<<<gemmBlocks, 256>>>(x, 0, W1, b1, N);
    aggregate_kernel<<<aggBlocks, 256>>>(N);
    // layer 2
    gemm_bias_kernel<<<gemmBlocks, 256>>>(x, 1, W2, b2, N);
    aggregate_kernel<<<aggBlocks, 256>>>(N);
    // layer 3
    gemm_bias_kernel<<<gemmBlocks, 256>>>(x, 1, W3, b3, N);
    aggregate_kernel<<<aggBlocks, 256>>>(N);

    // pooling + final linear
    pool_kernel<<<aggBlocks, 256>>>(batch, Wl, N);
    final_kernel<<<1, 64>>>(out, bl);
}

// round 4
// speedup vs baseline: 1.1374x; 1.1374x over previous
#include <cuda_runtime.h>
#include <cuda_bf16.h>
#include <stdint.h>

// Problem constants
#define MAXN 40000
#define MAXE 640000
#define NG   64
#define F    128   // feature dim (F_IN == H == 128)
#define SCAN_TILE 1024
#define MAXNB ((MAXN + SCAN_TILE - 1) / SCAN_TILE)   // 40

// ---------------- device scratch (no allocations allowed) ----------------
__device__ float g_bufA[(size_t)MAXN * F];   // GEMM output (dis-prescaled) / agg input
__device__ float g_bufB[(size_t)MAXN * F];   // agg output / next GEMM input
__device__ int   g_deg[MAXN];
__device__ float g_dis[MAXN];
__device__ int   g_rowptr[MAXN + 1];
__device__ int   g_tmp[MAXN];
__device__ int   g_csr[MAXE + MAXN];
__device__ int   g_blocksums[MAXNB + 1];
__device__ float g_gsum[NG];
__device__ float g_gcnt[NG];

// ---------------- init: deg=1 (self loop), tmp=0, graph accumulators=0 ----
__global__ void init_kernel(int n) {
    int i = blockIdx.x * blockDim.x + threadIdx.x;
    if (i < n) { g_deg[i] = 1; g_tmp[i] = 0; }
    if (i < NG) { g_gsum[i] = 0.f; g_gcnt[i] = 0.f; }
}

// ---------------- in-degree histogram over edge targets -------------------
__global__ void count_kernel(const int* __restrict__ col, int E, int n) {
    int e = blockIdx.x * blockDim.x + threadIdx.x;
    if (e < E) {
        unsigned c = (unsigned)col[e];
        if (c < (unsigned)n) atomicAdd(&g_deg[c], 1);
    }
}

// ---------------- scan phase A: block sums + dis = rsqrt(deg) -------------
__global__ __launch_bounds__(SCAN_TILE)
void scan_phaseA(int n) {
    __shared__ int sh[32];
    int tid = threadIdx.x, lane = tid & 31, wid = tid >> 5;
    int i = blockIdx.x * SCAN_TILE + tid;
    int v = (i < n) ? g_deg[i] : 0;
    if (i < n) g_dis[i] = rsqrtf((float)v);
    int x = v;
#pragma unroll
    for (int o = 16; o > 0; o >>= 1) x += __shfl_xor_sync(0xffffffffu, x, o);
    if (lane == 0) sh[wid] = x;
    __syncthreads();
    if (wid == 0) {
        int w = sh[lane];
#pragma unroll
        for (int o = 16; o > 0; o >>= 1) w += __shfl_xor_sync(0xffffffffu, w, o);
        if (lane == 0) g_blocksums[blockIdx.x] = w;
    }
}

// ---------------- scan phase B: exclusive scan of block sums --------------
__global__ void scan_phaseB(int nb, int n) {
    __shared__ int ws[2];
    int tid = threadIdx.x, lane = tid & 31, wid = tid >> 5;
    int v = (tid < nb) ? g_blocksums[tid] : 0;
    int x = v;
#pragma unroll
    for (int o = 1; o < 32; o <<= 1) {
        int y = __shfl_up_sync(0xffffffffu, x, o);
        if (lane >= o) x += y;
    }
    if (lane == 31) ws[wid] = x;
    __syncthreads();
    int off = (wid == 1) ? ws[0] : 0;
    int inc = x + off;
    if (tid < nb) g_blocksums[tid] = inc - v;   // exclusive prefix
    if (tid == nb - 1) g_rowptr[n] = inc;       // grand total
}

// ---------------- scan phase C: per-block exclusive rescan -> rowptr ------
__global__ __launch_bounds__(SCAN_TILE)
void scan_phaseC(int n) {
    __shared__ int sh[32];
    int tid = threadIdx.x, lane = tid & 31, wid = tid >> 5;
    int i = blockIdx.x * SCAN_TILE + tid;
    int v = (i < n) ? g_deg[i] : 0;
    int x = v;
#pragma unroll
    for (int o = 1; o < 32; o <<= 1) {
        int y = __shfl_up_sync(0xffffffffu, x, o);
        if (lane >= o) x += y;
    }
    if (lane == 31) sh[wid] = x;
    __syncthreads();
    if (wid == 0) {
        int w = sh[lane];
#pragma unroll
        for (int o = 1; o < 32; o <<= 1) {
            int y = __shfl_up_sync(0xffffffffu, w, o);
            if (lane >= o) w += y;
        }
        sh[lane] = w;
    }
    __syncthreads();
    int woff = (wid > 0) ? sh[wid - 1] : 0;
    if (i < n) g_rowptr[i] = g_blocksums[blockIdx.x] + woff + x - v;
}

// ---------------- scatter edges (+self loops) into CSR by destination -----
__global__ void scatter_kernel(const int* __restrict__ row,
                               const int* __restrict__ col,
                               int E, int n) {
    int idx = blockIdx.x * blockDim.x + threadIdx.x;
    int total = E + n;
    if (idx >= total) return;
    unsigned d, s;
    if (idx < E) { d = (unsigned)col[idx]; s = (unsigned)row[idx]; }
    else         { d = (unsigned)(idx - E); s = d; }
    if (d >= (unsigned)n || s >= (unsigned)n) return;
    int p = g_rowptr[d] + atomicAdd(&g_tmp[d], 1);
    g_csr[p] = (int)s;
}

// ------ SGEMM: g_bufA[r,:] = dis[r] * (A[r,:] @ W + bias)  (prescaled) ----
// useBuf=0: A = xExt (first layer). useBuf=1: A = g_bufB.
__global__ __launch_bounds__(256)
void gemm_bias_kernel(const float* __restrict__ xExt, int useBuf,
                      const float* __restrict__ W,
                      const float* __restrict__ bias, int M) {
    const float* __restrict__ A = useBuf ? (const float*)g_bufB : xExt;
    float* __restrict__ C = g_bufA;

    __shared__ float As[16][128];  // [k][m]
    __shared__ float Bs[16][128];  // [k][n]
    const int t = threadIdx.x;
    const int blockM = blockIdx.x * 128;
    const int tRow = (t >> 4) * 8;   // 0..120
    const int tCol = (t & 15) * 8;   // 0..120

    float acc[8][8];
#pragma unroll
    for (int i = 0; i < 8; i++)
#pragma unroll
        for (int j = 0; j < 8; j++) acc[i][j] = 0.f;

    for (int k0 = 0; k0 < 128; k0 += 16) {
#pragma unroll
        for (int l = 0; l < 2; l++) {
            int f = t + l * 256;
            int rl = f >> 2;
            int seg = (f & 3) * 4;
            int grow = blockM + rl;
            float4 v = make_float4(0.f, 0.f, 0.f, 0.f);
            if (grow < M)
                v = *(const float4*)(A + (size_t)grow * 128 + k0 + seg);
            As[seg + 0][rl] = v.x;
            As[seg + 1][rl] = v.y;
            As[seg + 2][rl] = v.z;
            As[seg + 3][rl] = v.w;
        }
#pragma unroll
        for (int l = 0; l < 2; l++) {
            int f = t + l * 256;
            int kr = f >> 5;
            int cs = (f & 31) * 4;
            float4 v = *(const float4*)(W + (size_t)(k0 + kr) * 128 + cs);
            *(float4*)(&Bs[kr][cs]) = v;
        }
        __syncthreads();
#pragma unroll
        for (int kk = 0; kk < 16; kk++) {
            float ra[8], rb[8];
#pragma unroll
            for (int i = 0; i < 8; i++) ra[i] = As[kk][tRow + i];
#pragma unroll
            for (int j = 0; j < 8; j++) rb[j] = Bs[kk][tCol + j];
#pragma unroll
            for (int i = 0; i < 8; i++)
#pragma unroll
                for (int j = 0; j < 8; j++)
                    acc[i][j] = fmaf(ra[i], rb[j], acc[i][j]);
        }
        __syncthreads();
    }
    float b0[8];
#pragma unroll
    for (int j = 0; j < 8; j++) b0[j] = bias[tCol + j];
#pragma unroll
    for (int i = 0; i < 8; i++) {
        int grow = blockM + tRow + i;
        if (grow < M) {
            float ds = g_dis[grow];   // prescale by source norm factor
            float4 v0, v1;
            v0.x = (acc[i][0] + b0[0]) * ds; v0.y = (acc[i][1] + b0[1]) * ds;
            v0.z = (acc[i][2] + b0[2]) * ds; v0.w = (acc[i][3] + b0[3]) * ds;
            v1.x = (acc[i][4] + b0[4]) * ds; v1.y = (acc[i][5] + b0[5]) * ds;
            v1.z = (acc[i][6] + b0[6]) * ds; v1.w = (acc[i][7] + b0[7]) * ds;
            float* cp = C + (size_t)grow * 128 + tCol;
            *(float4*)(cp)     = v0;
            *(float4*)(cp + 4) = v1;
        }
    }
}

// ------ CSR gather aggregation: g_bufB = relu(dis[d] * sum g_bufA[s]) -----
// (g_bufA rows already prescaled by dis[s])
__global__ __launch_bounds__(256)
void aggregate_kernel(int n) {
    int node = blockIdx.x * 8 + (threadIdx.x >> 5);
    if (node >= n) return;
    int lane = threadIdx.x & 31;
    const float* __restrict__ h = g_bufA;
    int s = g_rowptr[node];
    int e = g_rowptr[node + 1];
    float4 acc = make_float4(0.f, 0.f, 0.f, 0.f);
    int p = s;
    // 4-way unroll: 4 independent row gathers in flight (L2 latency hiding)
    for (; p + 4 <= e; p += 4) {
        int s0 = g_csr[p + 0];
        int s1 = g_csr[p + 1];
        int s2 = g_csr[p + 2];
        int s3 = g_csr[p + 3];
        float4 v0 = *(const float4*)(h + (size_t)s0 * 128 + lane * 4);
        float4 v1 = *(const float4*)(h + (size_t)s1 * 128 + lane * 4);
        float4 v2 = *(const float4*)(h + (size_t)s2 * 128 + lane * 4);
        float4 v3 = *(const float4*)(h + (size_t)s3 * 128 + lane * 4);
        acc.x += (v0.x + v1.x) + (v2.x + v3.x);
        acc.y += (v0.y + v1.y) + (v2.y + v3.y);
        acc.z += (v0.z + v1.z) + (v2.z + v3.z);
        acc.w += (v0.w + v1.w) + (v2.w + v3.w);
    }
    for (; p < e; p++) {
        int src = g_csr[p];
        float4 v = *(const float4*)(h + (size_t)src * 128 + lane * 4);
        acc.x += v.x; acc.y += v.y; acc.z += v.z; acc.w += v.w;
    }
    float dd = g_dis[node];
    acc.x = fmaxf(acc.x * dd, 0.f);
    acc.y = fmaxf(acc.y * dd, 0.f);
    acc.z = fmaxf(acc.z * dd, 0.f);
    acc.w = fmaxf(acc.w * dd, 0.f);
    *(float4*)(g_bufB + (size_t)node * 128 + lane * 4) = acc;
}

// ---------------- pooling: per-node dot with Wl, segment-sum by graph -----
__global__ __launch_bounds__(256)
void pool_kernel(const int* __restrict__ batch,
                 const float* __restrict__ Wl, int n) {
    int node = blockIdx.x * 8 + (threadIdx.x >> 5);
    if (node >= n) return;
    int lane = threadIdx.x & 31;
    float4 w = *(const float4*)(Wl + lane * 4);
    float4 v = *(const float4*)(g_bufB + (size_t)node * 128 + lane * 4);
    float sv = v.x * w.x + v.y * w.y + v.z * w.z + v.w * w.w;
#pragma unroll
    for (int o = 16; o > 0; o >>= 1) sv += __shfl_xor_sync(0xffffffffu, sv, o);
    if (lane == 0) {
        unsigned b = (unsigned)batch[node];
        if (b < NG) {
            atomicAdd(&g_gsum[b], sv);
            atomicAdd(&g_gcnt[b], 1.0f);
        }
    }
}

__global__ void final_kernel(float* __restrict__ out, const float* __restrict__ bl) {
    int g = threadIdx.x;
    if (g < NG) out[g] = g_gsum[g] / fmaxf(g_gcnt[g], 1.0f) + bl[0];
}

// --------------------------------------------------------------------------
extern "C" void kernel_launch(void* const* d_in, const int* in_sizes, int n_in,
                              void* d_out, int out_size) {
    // Expected order: x, edge_index, batch, [dropout_rate], W1,b1,W2,b2,W3,b3,Wl,bl
    const float* x     = (const float*)d_in[0];
    const int*   eidx  = (const int*)d_in[1];    // int32
    const int*   batch = (const int*)d_in[2];

    int wbase = (in_sizes[3] < 128) ? 4 : 3;
    const float* W1 = (const float*)d_in[wbase + 0];
    const float* b1 = (const float*)d_in[wbase + 1];
    const float* W2 = (const float*)d_in[wbase + 2];
    const float* b2 = (const float*)d_in[wbase + 3];
    const float* W3 = (const float*)d_in[wbase + 4];
    const float* b3 = (const float*)d_in[wbase + 5];
    const float* Wl = (const float*)d_in[wbase + 6];
    const float* bl = (const float*)d_in[wbase + 7];
    float* out = (float*)d_out;

    const int N = in_sizes[0] / F;          // 40000
    const int E = in_sizes[1] / 2;          // 640000
    const int* erow = eidx;                 // sources
    const int* ecol = eidx + E;             // targets
    const int NB = (N + SCAN_TILE - 1) / SCAN_TILE;

    const int T = 256;
    // 1) graph preprocessing -> CSR by destination
    init_kernel<<<(N + T - 1) / T, T>>>(N);
    count_kernel<<<(E + T - 1) / T, T>>>(ecol, E, N);
    scan_phaseA<<<NB, SCAN_TILE>>>(N);
    scan_phaseB<<<1, 64>>>(NB, N);
    scan_phaseC<<<NB, SCAN_TILE>>>(N);
    scatter_kernel<<<(E + N + T - 1) / T, T>>>(erow, ecol, E, N);

    const int gemmBlocks = (N + 127) / 128;
    const int aggBlocks  = (N + 7) / 8;

    // layer 1
    gemm_bias_kernel<<<gemmBlocks, 256>>>(x, 0, W1, b1, N);
    aggregate_kernel<<<aggBlocks, 256>>>(N);
    // layer 2
    gemm_bias_kernel<<<gemmBlocks, 256>>>(x, 1, W2, b2, N);
    aggregate_kernel<<<aggBlocks, 256>>>(N);
    // layer 3
    gemm_bias_kernel<<<gemmBlocks, 256>>>(x, 1, W3, b3, N);
    aggregate_kernel<<<aggBlocks, 256>>>(N);

    // pooling + final linear
    pool_kernel<<<aggBlocks, 256>>>(batch, Wl, N);
    final_kernel<<<1, 64>>>(out, bl);
}

// round 7
// speedup vs baseline: 1.2836x; 1.1285x over previous
#include <cuda_runtime.h>
#include <cuda_fp16.h>
#include <stdint.h>

// Problem constants
#define MAXN 40000
#define MAXE 640000
#define NG   64
#define F    128   // feature dim (F_IN == H == 128)
#define SCAN_TILE 1024
#define MAXNB ((MAXN + SCAN_TILE - 1) / SCAN_TILE)   // 40

// ---------------- device scratch (no allocations allowed) ----------------
__device__ __half g_hbuf[(size_t)MAXN * F];  // GEMM output (dis-prescaled), fp16
__device__ float  g_bufB[(size_t)MAXN * F];  // agg output (layers 1,2), fp32
__device__ int    g_deg[MAXN];
__device__ float  g_dis[MAXN];
__device__ int    g_rowptr[MAXN + 1];
__device__ int    g_tmp[MAXN];
__device__ int    g_csr[MAXE + MAXN];
__device__ int    g_blocksums[MAXNB];
__device__ float  g_gsum[NG];
__device__ float  g_gcnt[NG];

// -------- init: deg=1 (self loop), tmp=0, graph accums=0, rowptr[N] -------
__global__ void init_kernel(int n, int total) {
    int i = blockIdx.x * blockDim.x + threadIdx.x;
    if (i < n) { g_deg[i] = 1; g_tmp[i] = 0; }
    if (i < NG) { g_gsum[i] = 0.f; g_gcnt[i] = 0.f; }
    if (i == 0) g_rowptr[n] = total;
}

// ---------------- in-degree histogram over edge targets -------------------
__global__ void count_kernel(const int* __restrict__ col, int E, int n) {
    int e = blockIdx.x * blockDim.x + threadIdx.x;
    if (e < E) {
        unsigned c = (unsigned)col[e];
        if (c < (unsigned)n) atomicAdd(&g_deg[c], 1);
    }
}

// ---------------- scan phase A: block sums + dis = rsqrt(deg) -------------
__global__ __launch_bounds__(SCAN_TILE)
void scan_phaseA(int n) {
    __shared__ int sh[32];
    int tid = threadIdx.x, lane = tid & 31, wid = tid >> 5;
    int i = blockIdx.x * SCAN_TILE + tid;
    int v = (i < n) ? g_deg[i] : 0;
    if (i < n) g_dis[i] = rsqrtf((float)v);
    int x = v;
#pragma unroll
    for (int o = 16; o > 0; o >>= 1) x += __shfl_xor_sync(0xffffffffu, x, o);
    if (lane == 0) sh[wid] = x;
    __syncthreads();
    if (wid == 0) {
        int w = sh[lane];
#pragma unroll
        for (int o = 16; o > 0; o >>= 1) w += __shfl_xor_sync(0xffffffffu, w, o);
        if (lane == 0) g_blocksums[blockIdx.x] = w;
    }
}

// --- scan phase C: per-block rescan; block offset scanned inline (NB<=64) -
__global__ __launch_bounds__(SCAN_TILE)
void scan_phaseC(int n, int nb) {
    __shared__ int sh[32];
    __shared__ int bexcl[64];
    __shared__ int w0tot;
    int tid = threadIdx.x, lane = tid & 31, wid = tid >> 5;

    if (tid < 64) {
        int v = (tid < nb) ? g_blocksums[tid] : 0;
        int x = v;
#pragma unroll
        for (int o = 1; o < 32; o <<= 1) {
            int y = __shfl_up_sync(0xffffffffu, x, o);
            if (lane >= o) x += y;
        }
        if (tid == 31) w0tot = x;
        bexcl[tid] = x - v;
    }
    __syncthreads();
    if (tid >= 32 && tid < 64) bexcl[tid] += w0tot;
    __syncthreads();
    int blockOff = bexcl[blockIdx.x];

    int i = blockIdx.x * SCAN_TILE + tid;
    int v = (i < n) ? g_deg[i] : 0;
    int x = v;
#pragma unroll
    for (int o = 1; o < 32; o <<= 1) {
        int y = __shfl_up_sync(0xffffffffu, x, o);
        if (lane >= o) x += y;
    }
    if (lane == 31) sh[wid] = x;
    __syncthreads();
    if (wid == 0) {
        int w = sh[lane];
#pragma unroll
        for (int o = 1; o < 32; o <<= 1) {
            int y = __shfl_up_sync(0xffffffffu, w, o);
            if (lane >= o) w += y;
        }
        sh[lane] = w;
    }
    __syncthreads();
    int woff = (wid > 0) ? sh[wid - 1] : 0;
    if (i < n) g_rowptr[i] = blockOff + woff + x - v;
}

// ---------------- scatter edges (+self loops) into CSR by destination -----
__global__ void scatter_kernel(const int* __restrict__ row,
                               const int* __restrict__ col,
                               int E, int n) {
    int idx = blockIdx.x * blockDim.x + threadIdx.x;
    int total = E + n;
    if (idx >= total) return;
    unsigned d, s;
    if (idx < E) { d = (unsigned)col[idx]; s = (unsigned)row[idx]; }
    else         { d = (unsigned)(idx - E); s = d; }
    if (d >= (unsigned)n || s >= (unsigned)n) return;
    int p = g_rowptr[d] + atomicAdd(&g_tmp[d], 1);
    g_csr[p] = (int)s;
}

// ------ SGEMM: g_hbuf[r,:] = half( dis[r] * (A[r,:] @ W + bias) ) ---------
// useBuf=0: A = xExt (first layer). useBuf=1: A = g_bufB.
__global__ __launch_bounds__(256)
void gemm_bias_kernel(const float* __restrict__ xExt, int useBuf,
                      const float* __restrict__ W,
                      const float* __restrict__ bias, int M) {
    const float* __restrict__ A = useBuf ? (const float*)g_bufB : xExt;

    __shared__ float As[16][128];  // [k][m]
    __shared__ float Bs[16][128];  // [k][n]
    const int t = threadIdx.x;
    const int blockM = blockIdx.x * 128;
    const int tRow = (t >> 4) * 8;   // 0..120
    const int tCol = (t & 15) * 8;   // 0..120

    float acc[8][8];
#pragma unroll
    for (int i = 0; i < 8; i++)
#pragma unroll
        for (int j = 0; j < 8; j++) acc[i][j] = 0.f;

    for (int k0 = 0; k0 < 128; k0 += 16) {
#pragma unroll
        for (int l = 0; l < 2; l++) {
            int f = t + l * 256;
            int rl = f >> 2;
            int seg = (f & 3) * 4;
            int grow = blockM + rl;
            float4 v = make_float4(0.f, 0.f, 0.f, 0.f);
            if (grow < M)
                v = *(const float4*)(A + (size_t)grow * 128 + k0 + seg);
            As[seg + 0][rl] = v.x;
            As[seg + 1][rl] = v.y;
            As[seg + 2][rl] = v.z;
            As[seg + 3][rl] = v.w;
        }
#pragma unroll
        for (int l = 0; l < 2; l++) {
            int f = t + l * 256;
            int kr = f >> 5;
            int cs = (f & 31) * 4;
            float4 v = *(const float4*)(W + (size_t)(k0 + kr) * 128 + cs);
            *(float4*)(&Bs[kr][cs]) = v;
        }
        __syncthreads();
#pragma unroll
        for (int kk = 0; kk < 16; kk++) {
            float ra[8], rb[8];
#pragma unroll
            for (int i = 0; i < 8; i++) ra[i] = As[kk][tRow + i];
#pragma unroll
            for (int j = 0; j < 8; j++) rb[j] = Bs[kk][tCol + j];
#pragma unroll
            for (int i = 0; i < 8; i++)
#pragma unroll
                for (int j = 0; j < 8; j++)
                    acc[i][j] = fmaf(ra[i], rb[j], acc[i][j]);
        }
        __syncthreads();
    }
    float b0[8];
#pragma unroll
    for (int j = 0; j < 8; j++) b0[j] = bias[tCol + j];
#pragma unroll
    for (int i = 0; i < 8; i++) {
        int grow = blockM + tRow + i;
        if (grow < M) {
            float ds = g_dis[grow];   // prescale by source norm factor
            __half2 p0 = __floats2half2_rn((acc[i][0] + b0[0]) * ds, (acc[i][1] + b0[1]) * ds);
            __half2 p1 = __floats2half2_rn((acc[i][2] + b0[2]) * ds, (acc[i][3] + b0[3]) * ds);
            __half2 p2 = __floats2half2_rn((acc[i][4] + b0[4]) * ds, (acc[i][5] + b0[5]) * ds);
            __half2 p3 = __floats2half2_rn((acc[i][6] + b0[6]) * ds, (acc[i][7] + b0[7]) * ds);
            uint4 pk;
            pk.x = *reinterpret_cast<unsigned*>(&p0);
            pk.y = *reinterpret_cast<unsigned*>(&p1);
            pk.z = *reinterpret_cast<unsigned*>(&p2);
            pk.w = *reinterpret_cast<unsigned*>(&p3);
            *(uint4*)(g_hbuf + (size_t)grow * 128 + tCol) = pk;
        }
    }
}

// ------ CSR gather aggregation over fp16 rows, fp32 accumulate ------------
// Each lane covers 4 features (uint2 = 4 halves); 32 lanes x 4 = 128. ✓
// out[d] = relu(dis[d] * sum_{s in N(d)} hbuf[s])  (hbuf prescaled by dis[s])
// POOL: instead of writing g_bufB, dot with Wl and segment-add into g_gsum.
__device__ __forceinline__ void accum_row(float acc[4], const __half* rowp, int lane) {
    uint2 u = *(const uint2*)(rowp + lane * 4);
    __half2 h0 = *reinterpret_cast<__half2*>(&u.x);
    __half2 h1 = *reinterpret_cast<__half2*>(&u.y);
    float2 f0 = __half22float2(h0);
    float2 f1 = __half22float2(h1);
    acc[0] += f0.x; acc[1] += f0.y; acc[2] += f1.x; acc[3] += f1.y;
}

template <bool POOL>
__global__ __launch_bounds__(256)
void aggregate_kernel(int n, const int* __restrict__ batch,
                      const float* __restrict__ Wl) {
    int node = blockIdx.x * 8 + (threadIdx.x >> 5);
    if (node >= n) return;
    int lane = threadIdx.x & 31;
    const __half* __restrict__ h = g_hbuf;
    int s = g_rowptr[node];
    int e = g_rowptr[node + 1];
    float acc[4] = {0.f, 0.f, 0.f, 0.f};

    int p = s;
    for (; p + 4 <= e; p += 4) {   // 4 independent row gathers in flight
        int s0 = g_csr[p + 0];
        int s1 = g_csr[p + 1];
        int s2 = g_csr[p + 2];
        int s3 = g_csr[p + 3];
        accum_row(acc, h + (size_t)s0 * 128, lane);
        accum_row(acc, h + (size_t)s1 * 128, lane);
        accum_row(acc, h + (size_t)s2 * 128, lane);
        accum_row(acc, h + (size_t)s3 * 128, lane);
    }
    for (; p < e; p++)
        accum_row(acc, h + (size_t)g_csr[p] * 128, lane);

    float dd = g_dis[node];
#pragma unroll
    for (int j = 0; j < 4; j++) acc[j] = fmaxf(acc[j] * dd, 0.f);

    if (POOL) {
        float4 w = *(const float4*)(Wl + lane * 4);
        float sv = acc[0] * w.x + acc[1] * w.y + acc[2] * w.z + acc[3] * w.w;
#pragma unroll
        for (int o = 16; o > 0; o >>= 1) sv += __shfl_xor_sync(0xffffffffu, sv, o);
        if (lane == 0) {
            unsigned b = (unsigned)batch[node];
            if (b < NG) {
                atomicAdd(&g_gsum[b], sv);
                atomicAdd(&g_gcnt[b], 1.0f);
            }
        }
    } else {
        float4 o0 = make_float4(acc[0], acc[1], acc[2], acc[3]);
        *(float4*)(g_bufB + (size_t)node * 128 + lane * 4) = o0;
    }
}

__global__ void final_kernel(float* __restrict__ out, const float* __restrict__ bl) {
    int g = threadIdx.x;
    if (g < NG) out[g] = g_gsum[g] / fmaxf(g_gcnt[g], 1.0f) + bl[0];
}

// --------------------------------------------------------------------------
extern "C" void kernel_launch(void* const* d_in, const int* in_sizes, int n_in,
                              void* d_out, int out_size) {
    // Expected order: x, edge_index, batch, [dropout_rate], W1,b1,W2,b2,W3,b3,Wl,bl
    const float* x     = (const float*)d_in[0];
    const int*   eidx  = (const int*)d_in[1];    // int32
    const int*   batch = (const int*)d_in[2];

    int wbase = (in_sizes[3] < 128) ? 4 : 3;
    const float* W1 = (const float*)d_in[wbase + 0];
    const float* b1 = (const float*)d_in[wbase + 1];
    const float* W2 = (const float*)d_in[wbase + 2];
    const float* b2 = (const float*)d_in[wbase + 3];
    const float* W3 = (const float*)d_in[wbase + 4];
    const float* b3 = (const float*)d_in[wbase + 5];
    const float* Wl = (const float*)d_in[wbase + 6];
    const float* bl = (const float*)d_in[wbase + 7];
    float* out = (float*)d_out;

    const int N = in_sizes[0] / F;          // 40000
    const int E = in_sizes[1] / 2;          // 640000
    const int* erow = eidx;                 // sources
    const int* ecol = eidx + E;             // targets
    const int NB = (N + SCAN_TILE - 1) / SCAN_TILE;

    const int T = 256;
    // 1) graph preprocessing -> CSR by destination
    init_kernel<<<(N + T - 1) / T, T>>>(N, E + N);
    count_kernel<<<(E + T - 1) / T, T>>>(ecol, E, N);
    scan_phaseA<<<NB, SCAN_TILE>>>(N);
    scan_phaseC<<<NB, SCAN_TILE>>>(N, NB);
    scatter_kernel<<<(E + N + T - 1) / T, T>>>(erow, ecol, E, N);

    const int gemmBlocks = (N + 127) / 128;
    const int aggBlocks  = (N + 7) / 8;

    // layer 1
    gemm_bias_kernel<<<gemmBlocks, 256>>>(x, 0, W1, b1, N);
    aggregate_kernel<false><<<aggBlocks, 256>>>(N, batch, Wl);
    // layer 2
    gemm_bias_kernel<<<gemmBlocks, 256>>>(x, 1, W2, b2, N);
    aggregate_kernel<false><<<aggBlocks, 256>>>(N, batch, Wl);
    // layer 3 (+ fused global mean pool partial sums)
    gemm_bias_kernel<<<gemmBlocks, 256>>>(x, 1, W3, b3, N);
    aggregate_kernel<true><<<aggBlocks, 256>>>(N, batch, Wl);

    final_kernel<<<1, 64>>>(out, bl);
}

// round 8
// speedup vs baseline: 1.9774x; 1.5405x over previous
#include <cuda_runtime.h>
#include <cuda_fp16.h>
#include <stdint.h>

// Problem constants
#define MAXN 40000
#define MAXE 640000
#define NG   64
#define F    128
#define SCAN_TILE 1024
#define MAXNB ((MAXN + SCAN_TILE - 1) / SCAN_TILE)   // 40

// ---------------- device scratch ----------------
__device__ __half g_xh[(size_t)MAXN * F];    // fp16 ping: x converted / agg output
__device__ __half g_hbuf[(size_t)MAXN * F];  // fp16 pong: GEMM output (dis-prescaled)
__device__ int    g_deg[MAXN];
__device__ float  g_dis[MAXN];
__device__ int    g_rowptr[MAXN + 1];
__device__ int    g_tmp[MAXN];
__device__ int    g_csr[MAXE + MAXN];
__device__ int    g_blocksums[MAXNB];
__device__ float  g_gsum[NG];
__device__ float  g_gcnt[NG];

// -------- init --------
__global__ void init_kernel(int n, int total) {
    int i = blockIdx.x * blockDim.x + threadIdx.x;
    if (i < n) { g_deg[i] = 1; g_tmp[i] = 0; }
    if (i < NG) { g_gsum[i] = 0.f; g_gcnt[i] = 0.f; }
    if (i == 0) g_rowptr[n] = total;
}

// -------- convert x (fp32) -> g_xh (fp16), vectorized --------
__global__ void convertx_kernel(const float* __restrict__ x, int total4) {
    int i = blockIdx.x * blockDim.x + threadIdx.x;   // handles 4 floats
    if (i < total4) {
        float4 v = *(const float4*)(x + (size_t)i * 4);
        __half2 h0 = __floats2half2_rn(v.x, v.y);
        __half2 h1 = __floats2half2_rn(v.z, v.w);
        uint2 pk;
        pk.x = *reinterpret_cast<unsigned*>(&h0);
        pk.y = *reinterpret_cast<unsigned*>(&h1);
        *(uint2*)(g_xh + (size_t)i * 4) = pk;
    }
}

// -------- degree histogram --------
__global__ void count_kernel(const int* __restrict__ col, int E, int n) {
    int e = blockIdx.x * blockDim.x + threadIdx.x;
    if (e < E) {
        unsigned c = (unsigned)col[e];
        if (c < (unsigned)n) atomicAdd(&g_deg[c], 1);
    }
}

// -------- scan phase A --------
__global__ __launch_bounds__(SCAN_TILE)
void scan_phaseA(int n) {
    __shared__ int sh[32];
    int tid = threadIdx.x, lane = tid & 31, wid = tid >> 5;
    int i = blockIdx.x * SCAN_TILE + tid;
    int v = (i < n) ? g_deg[i] : 0;
    if (i < n) g_dis[i] = rsqrtf((float)v);
    int x = v;
#pragma unroll
    for (int o = 16; o > 0; o >>= 1) x += __shfl_xor_sync(0xffffffffu, x, o);
    if (lane == 0) sh[wid] = x;
    __syncthreads();
    if (wid == 0) {
        int w = sh[lane];
#pragma unroll
        for (int o = 16; o > 0; o >>= 1) w += __shfl_xor_sync(0xffffffffu, w, o);
        if (lane == 0) g_blocksums[blockIdx.x] = w;
    }
}

// -------- scan phase C --------
__global__ __launch_bounds__(SCAN_TILE)
void scan_phaseC(int n, int nb) {
    __shared__ int sh[32];
    __shared__ int bexcl[64];
    __shared__ int w0tot;
    int tid = threadIdx.x, lane = tid & 31, wid = tid >> 5;

    if (tid < 64) {
        int v = (tid < nb) ? g_blocksums[tid] : 0;
        int x = v;
#pragma unroll
        for (int o = 1; o < 32; o <<= 1) {
            int y = __shfl_up_sync(0xffffffffu, x, o);
            if (lane >= o) x += y;
        }
        if (tid == 31) w0tot = x;
        bexcl[tid] = x - v;
    }
    __syncthreads();
    if (tid >= 32 && tid < 64) bexcl[tid] += w0tot;
    __syncthreads();
    int blockOff = bexcl[blockIdx.x];

    int i = blockIdx.x * SCAN_TILE + tid;
    int v = (i < n) ? g_deg[i] : 0;
    int x = v;
#pragma unroll
    for (int o = 1; o < 32; o <<= 1) {
        int y = __shfl_up_sync(0xffffffffu, x, o);
        if (lane >= o) x += y;
    }
    if (lane == 31) sh[wid] = x;
    __syncthreads();
    if (wid == 0) {
        int w = sh[lane];
#pragma unroll
        for (int o = 1; o < 32; o <<= 1) {
            int y = __shfl_up_sync(0xffffffffu, w, o);
            if (lane >= o) w += y;
        }
        sh[lane] = w;
    }
    __syncthreads();
    int woff = (wid > 0) ? sh[wid - 1] : 0;
    if (i < n) g_rowptr[i] = blockOff + woff + x - v;
}

// -------- scatter into CSR --------
__global__ void scatter_kernel(const int* __restrict__ row,
                               const int* __restrict__ col,
                               int E, int n) {
    int idx = blockIdx.x * blockDim.x + threadIdx.x;
    int total = E + n;
    if (idx >= total) return;
    unsigned d, s;
    if (idx < E) { d = (unsigned)col[idx]; s = (unsigned)row[idx]; }
    else         { d = (unsigned)(idx - E); s = d; }
    if (d >= (unsigned)n || s >= (unsigned)n) return;
    int p = g_rowptr[d] + atomicAdd(&g_tmp[d], 1);
    g_csr[p] = (int)s;
}

// ======== Tensor-core GEMM: g_hbuf = half( dis * (g_xh @ W + bias) ) ========
// Block: 128 rows x 128 cols, K=128 in 2 stages of 64. 8 warps = 4(m) x 2(n);
// warp tile 32x64 = 2(m16) x 8(n8) mma fragments, fp16 x fp16 -> fp32.
__device__ __forceinline__ void ldsm_x4(uint32_t* r, const __half* p) {
    uint32_t addr = (uint32_t)__cvta_generic_to_shared(p);
    asm volatile("ldmatrix.sync.aligned.m8n8.x4.shared.b16 {%0,%1,%2,%3}, [%4];"
                 : "=r"(r[0]), "=r"(r[1]), "=r"(r[2]), "=r"(r[3]) : "r"(addr));
}
__device__ __forceinline__ void ldsm_x2t(uint32_t* r, const __half* p) {
    uint32_t addr = (uint32_t)__cvta_generic_to_shared(p);
    asm volatile("ldmatrix.sync.aligned.m8n8.x2.trans.shared.b16 {%0,%1}, [%2];"
                 : "=r"(r[0]), "=r"(r[1]) : "r"(addr));
}
__device__ __forceinline__ void mma16816(float* c, const uint32_t* a, const uint32_t* b) {
    asm volatile("mma.sync.aligned.m16n8k16.row.col.f32.f16.f16.f32 "
                 "{%0,%1,%2,%3}, {%4,%5,%6,%7}, {%8,%9}, {%0,%1,%2,%3};"
                 : "+f"(c[0]), "+f"(c[1]), "+f"(c[2]), "+f"(c[3])
                 : "r"(a[0]), "r"(a[1]), "r"(a[2]), "r"(a[3]), "r"(b[0]), "r"(b[1]));
}

#define LDA 72   // 64 + 8 halves pad; row stride 144 B (16B aligned)
#define LDB 136  // 128 + 8 halves pad; row stride 272 B (16B aligned)

__global__ __launch_bounds__(256)
void gemm_tc_kernel(const float* __restrict__ W,
                    const float* __restrict__ bias, int M) {
    __shared__ __half sA[128 * LDA];
    __shared__ __half sB[64 * LDB];
    __shared__ float sBias[128];

    const int t = threadIdx.x;
    const int wid = t >> 5, lane = t & 31;
    const int blockM = blockIdx.x * 128;
    const int warpM = (wid >> 1) * 32;   // 0,32,64,96
    const int warpN = (wid & 1) * 64;    // 0,64

    if (t < 128) sBias[t] = bias[t];

    float c[2][8][4];
#pragma unroll
    for (int mi = 0; mi < 2; mi++)
#pragma unroll
        for (int ni = 0; ni < 8; ni++)
#pragma unroll
            for (int q = 0; q < 4; q++) c[mi][ni][q] = 0.f;

#pragma unroll
    for (int stage = 0; stage < 2; stage++) {
        const int kOff = stage * 64;
        // load A tile: 128 rows x 64 halves (fp16 in global)
#pragma unroll
        for (int l = 0; l < 4; l++) {
            int idx = (t + l * 256) * 8;       // half index in 128x64
            int row = idx >> 6;
            int col = idx & 63;
            int grow = blockM + row;
            uint4 v = make_uint4(0u, 0u, 0u, 0u);
            if (grow < M)
                v = *(const uint4*)(g_xh + (size_t)grow * 128 + kOff + col);
            *(uint4*)(sA + row * LDA + col) = v;
        }
        // load W tile: 64 rows x 128 cols, convert fp32 -> fp16
#pragma unroll
        for (int l = 0; l < 8; l++) {
            int idx = (t + l * 256) * 4;       // elem index in 64x128
            int row = idx >> 7;
            int col = idx & 127;
            float4 v = *(const float4*)(W + (size_t)(kOff + row) * 128 + col);
            __half2 h0 = __floats2half2_rn(v.x, v.y);
            __half2 h1 = __floats2half2_rn(v.z, v.w);
            uint2 pk;
            pk.x = *reinterpret_cast<unsigned*>(&h0);
            pk.y = *reinterpret_cast<unsigned*>(&h1);
            *(uint2*)(sB + row * LDB + col) = pk;
        }
        __syncthreads();

#pragma unroll
        for (int ks = 0; ks < 4; ks++) {
            const int kb = ks * 16;
            uint32_t a[2][4];
#pragma unroll
            for (int mi = 0; mi < 2; mi++) {
                int r = warpM + mi * 16 + (lane & 15);
                int cc = kb + ((lane >> 4) << 3);
                ldsm_x4(a[mi], sA + r * LDA + cc);
            }
#pragma unroll
            for (int ni = 0; ni < 8; ni++) {
                uint32_t b[2];
                int r = kb + (lane & 15);
                int cc = warpN + ni * 8;
                ldsm_x2t(b, sB + r * LDB + cc);
                mma16816(c[0][ni], a[0], b);
                mma16816(c[1][ni], a[1], b);
            }
        }
        __syncthreads();
    }

    // epilogue: bias, prescale by dis[row], fp16 store
#pragma unroll
    for (int mi = 0; mi < 2; mi++) {
        int rBase = blockM + warpM + mi * 16 + (lane >> 2);
#pragma unroll
        for (int hh = 0; hh < 2; hh++) {
            int r = rBase + hh * 8;
            if (r < M) {
                float ds = g_dis[r];
#pragma unroll
                for (int ni = 0; ni < 8; ni++) {
                    int col = warpN + ni * 8 + (lane & 3) * 2;
                    float v0 = (c[mi][ni][hh * 2 + 0] + sBias[col]) * ds;
                    float v1 = (c[mi][ni][hh * 2 + 1] + sBias[col + 1]) * ds;
                    __half2 hv = __floats2half2_rn(v0, v1);
                    *(__half2*)(g_hbuf + (size_t)r * 128 + col) = hv;
                }
            }
        }
    }
}

// ======== CSR gather aggregation (fp16 rows, fp32 accumulate) ========
// Each lane covers 4 features; 32 lanes x 4 = 128.
__device__ __forceinline__ void accum_row(float acc[4], const __half* rowp, int lane) {
    uint2 u = *(const uint2*)(rowp + lane * 4);
    __half2 h0 = *reinterpret_cast<__half2*>(&u.x);
    __half2 h1 = *reinterpret_cast<__half2*>(&u.y);
    float2 f0 = __half22float2(h0);
    float2 f1 = __half22float2(h1);
    acc[0] += f0.x; acc[1] += f0.y; acc[2] += f1.x; acc[3] += f1.y;
}

template <bool POOL>
__global__ __launch_bounds__(256)
void aggregate_kernel(int n, const int* __restrict__ batch,
                      const float* __restrict__ Wl) {
    int node = blockIdx.x * 8 + (threadIdx.x >> 5);
    if (node >= n) return;
    int lane = threadIdx.x & 31;
    const __half* __restrict__ h = g_hbuf;
    int s = g_rowptr[node];
    int e = g_rowptr[node + 1];
    float acc[4] = {0.f, 0.f, 0.f, 0.f};

    int p = s;
    for (; p + 4 <= e; p += 4) {
        int s0 = g_csr[p + 0];
        int s1 = g_csr[p + 1];
        int s2 = g_csr[p + 2];
        int s3 = g_csr[p + 3];
        accum_row(acc, h + (size_t)s0 * 128, lane);
        accum_row(acc, h + (size_t)s1 * 128, lane);
        accum_row(acc, h + (size_t)s2 * 128, lane);
        accum_row(acc, h + (size_t)s3 * 128, lane);
    }
    for (; p < e; p++)
        accum_row(acc, h + (size_t)g_csr[p] * 128, lane);

    float dd = g_dis[node];
#pragma unroll
    for (int j = 0; j < 4; j++) acc[j] = fmaxf(acc[j] * dd, 0.f);

    if (POOL) {
        float4 w = *(const float4*)(Wl + lane * 4);
        float sv = acc[0] * w.x + acc[1] * w.y + acc[2] * w.z + acc[3] * w.w;
#pragma unroll
        for (int o = 16; o > 0; o >>= 1) sv += __shfl_xor_sync(0xffffffffu, sv, o);
        if (lane == 0) {
            unsigned b = (unsigned)batch[node];
            if (b < NG) {
                atomicAdd(&g_gsum[b], sv);
                atomicAdd(&g_gcnt[b], 1.0f);
            }
        }
    } else {
        __half2 o0 = __floats2half2_rn(acc[0], acc[1]);
        __half2 o1 = __floats2half2_rn(acc[2], acc[3]);
        uint2 pk;
        pk.x = *reinterpret_cast<unsigned*>(&o0);
        pk.y = *reinterpret_cast<unsigned*>(&o1);
        *(uint2*)(g_xh + (size_t)node * 128 + lane * 4) = pk;
    }
}

__global__ void final_kernel(float* __restrict__ out, const float* __restrict__ bl) {
    int g = threadIdx.x;
    if (g < NG) out[g] = g_gsum[g] / fmaxf(g_gcnt[g], 1.0f) + bl[0];
}

// --------------------------------------------------------------------------
extern "C" void kernel_launch(void* const* d_in, const int* in_sizes, int n_in,
                              void* d_out, int out_size) {
    const float* x     = (const float*)d_in[0];
    const int*   eidx  = (const int*)d_in[1];
    const int*   batch = (const int*)d_in[2];

    int wbase = (in_sizes[3] < 128) ? 4 : 3;
    const float* W1 = (const float*)d_in[wbase + 0];
    const float* b1 = (const float*)d_in[wbase + 1];
    const float* W2 = (const float*)d_in[wbase + 2];
    const float* b2 = (const float*)d_in[wbase + 3];
    const float* W3 = (const float*)d_in[wbase + 4];
    const float* b3 = (const float*)d_in[wbase + 5];
    const float* Wl = (const float*)d_in[wbase + 6];
    const float* bl = (const float*)d_in[wbase + 7];
    float* out = (float*)d_out;

    const int N = in_sizes[0] / F;          // 40000
    const int E = in_sizes[1] / 2;          // 640000
    const int* erow = eidx;
    const int* ecol = eidx + E;
    const int NB = (N + SCAN_TILE - 1) / SCAN_TILE;

    const int T = 256;
    init_kernel<<<(N + T - 1) / T, T>>>(N, E + N);
    convertx_kernel<<<(N * F / 4 + T - 1) / T, T>>>(x, N * F / 4);
    count_kernel<<<(E + T - 1) / T, T>>>(ecol, E, N);
    scan_phaseA<<<NB, SCAN_TILE>>>(N);
    scan_phaseC<<<NB, SCAN_TILE>>>(N, NB);
    scatter_kernel<<<(E + N + T - 1) / T, T>>>(erow, ecol, E, N);

    const int gemmBlocks = (N + 127) / 128;
    const int aggBlocks  = (N + 7) / 8;

    // layer 1
    gemm_tc_kernel<<<gemmBlocks, 256>>>(W1, b1, N);
    aggregate_kernel<false><<<aggBlocks, 256>>>(N, batch, Wl);
    // layer 2
    gemm_tc_kernel<<<gemmBlocks, 256>>>(W2, b2, N);
    aggregate_kernel<false><<<aggBlocks, 256>>>(N, batch, Wl);
    // layer 3 (+ fused global mean pool)
    gemm_tc_kernel<<<gemmBlocks, 256>>>(W3, b3, N);
    aggregate_kernel<true><<<aggBlocks, 256>>>(N, batch, Wl);

    final_kernel<<<1, 64>>>(out, bl);
}

// round 9
// speedup vs baseline: 1.9803x; 1.0015x over previous
#include <cuda_runtime.h>
#include <cuda_fp16.h>
#include <stdint.h>

// Problem constants
#define MAXN 40000
#define MAXE 640000
#define NG   64
#define F    128
#define SCAN_TILE 1024
#define MAXNB ((MAXN + SCAN_TILE - 1) / SCAN_TILE)   // 40

// ---------------- device scratch (zero at load; each call restores zeros) --
__device__ __half g_xh[(size_t)MAXN * F];    // fp16 ping: x converted / agg output
__device__ __half g_hbuf[(size_t)MAXN * F];  // fp16 pong: GEMM output (prescaled)
__device__ int    g_deg[MAXN];               // edge-count only; MUST be 0 at entry
__device__ float  g_dis[MAXN];
__device__ int    g_rowptr[MAXN + 1];
__device__ int    g_tmp[MAXN];               // MUST be 0 at entry
__device__ int    g_csr[MAXE + MAXN];
__device__ int    g_blocksums[MAXNB];
__device__ float  g_gsum[NG];                // MUST be 0 at entry
__device__ float  g_gcnt[NG];                // MUST be 0 at entry

// -------- convert x (fp32) -> g_xh (fp16), vectorized --------
__global__ void convertx_kernel(const float* __restrict__ x, int total4) {
    int i = blockIdx.x * blockDim.x + threadIdx.x;   // handles 4 floats
    if (i < total4) {
        float4 v = *(const float4*)(x + (size_t)i * 4);
        __half2 h0 = __floats2half2_rn(v.x, v.y);
        __half2 h1 = __floats2half2_rn(v.z, v.w);
        uint2 pk;
        pk.x = *reinterpret_cast<unsigned*>(&h0);
        pk.y = *reinterpret_cast<unsigned*>(&h1);
        *(uint2*)(g_xh + (size_t)i * 4) = pk;
    }
}

// -------- degree histogram (2 edges per thread) --------
__global__ void count_kernel(const int* __restrict__ col, int E, int n) {
    int i = blockIdx.x * blockDim.x + threadIdx.x;
    int e = i * 2;
    if (e + 1 < E) {
        int2 c2 = *(const int2*)(col + e);
        if ((unsigned)c2.x < (unsigned)n) atomicAdd(&g_deg[c2.x], 1);
        if ((unsigned)c2.y < (unsigned)n) atomicAdd(&g_deg[c2.y], 1);
    } else if (e < E) {
        unsigned c = (unsigned)col[e];
        if (c < (unsigned)n) atomicAdd(&g_deg[c], 1);
    }
}

// -------- scan phase A: block sums of (deg+1) + dis = rsqrt(deg+1) --------
__global__ __launch_bounds__(SCAN_TILE)
void scan_phaseA(int n) {
    __shared__ int sh[32];
    int tid = threadIdx.x, lane = tid & 31, wid = tid >> 5;
    int i = blockIdx.x * SCAN_TILE + tid;
    int v = (i < n) ? (g_deg[i] + 1) : 0;   // +1 = self loop
    if (i < n) g_dis[i] = rsqrtf((float)v);
    int x = v;
#pragma unroll
    for (int o = 16; o > 0; o >>= 1) x += __shfl_xor_sync(0xffffffffu, x, o);
    if (lane == 0) sh[wid] = x;
    __syncthreads();
    if (wid == 0) {
        int w = sh[lane];
#pragma unroll
        for (int o = 16; o > 0; o >>= 1) w += __shfl_xor_sync(0xffffffffu, w, o);
        if (lane == 0) g_blocksums[blockIdx.x] = w;
    }
}

// -------- scan phase C: rowptr (inline block-offset scan, NB<=64) --------
__global__ __launch_bounds__(SCAN_TILE)
void scan_phaseC(int n, int nb) {
    __shared__ int sh[32];
    __shared__ int bexcl[64];
    __shared__ int w0tot;
    int tid = threadIdx.x, lane = tid & 31, wid = tid >> 5;

    if (tid < 64) {
        int v = (tid < nb) ? g_blocksums[tid] : 0;
        int x = v;
#pragma unroll
        for (int o = 1; o < 32; o <<= 1) {
            int y = __shfl_up_sync(0xffffffffu, x, o);
            if (lane >= o) x += y;
        }
        if (tid == 31) w0tot = x;
        bexcl[tid] = x - v;
    }
    __syncthreads();
    if (tid >= 32 && tid < 64) bexcl[tid] += w0tot;
    __syncthreads();
    int blockOff = bexcl[blockIdx.x];
    // grand total -> rowptr[n] (all blocks write the same value)
    if (tid == 0 && blockIdx.x == 0)
        g_rowptr[n] = bexcl[nb - 1] + g_blocksums[nb - 1];

    int i = blockIdx.x * SCAN_TILE + tid;
    int v = (i < n) ? (g_deg[i] + 1) : 0;
    int x = v;
#pragma unroll
    for (int o = 1; o < 32; o <<= 1) {
        int y = __shfl_up_sync(0xffffffffu, x, o);
        if (lane >= o) x += y;
    }
    if (lane == 31) sh[wid] = x;
    __syncthreads();
    if (wid == 0) {
        int w = sh[lane];
#pragma unroll
        for (int o = 1; o < 32; o <<= 1) {
            int y = __shfl_up_sync(0xffffffffu, w, o);
            if (lane >= o) w += y;
        }
        sh[lane] = w;
    }
    __syncthreads();
    int woff = (wid > 0) ? sh[wid - 1] : 0;
    if (i < n) g_rowptr[i] = blockOff + woff + x - v;
}

// -------- scatter edges (+self loops) into CSR, 2 items per thread --------
__global__ void scatter_kernel(const int* __restrict__ row,
                               const int* __restrict__ col,
                               int E, int n) {
    int i = blockIdx.x * blockDim.x + threadIdx.x;
    int total = E + n;
#pragma unroll
    for (int q = 0; q < 2; q++) {
        int idx = i * 2 + q;
        if (idx >= total) return;
        unsigned d, s;
        if (idx < E) { d = (unsigned)col[idx]; s = (unsigned)row[idx]; }
        else         { d = (unsigned)(idx - E); s = d; }
        if (d >= (unsigned)n || s >= (unsigned)n) continue;
        int p = g_rowptr[d] + atomicAdd(&g_tmp[d], 1);
        g_csr[p] = (int)s;
    }
}

// ======== Tensor-core GEMM: g_hbuf = half( dis * (g_xh @ W + bias) ) ========
__device__ __forceinline__ void ldsm_x4(uint32_t* r, const __half* p) {
    uint32_t addr = (uint32_t)__cvta_generic_to_shared(p);
    asm volatile("ldmatrix.sync.aligned.m8n8.x4.shared.b16 {%0,%1,%2,%3}, [%4];"
                 : "=r"(r[0]), "=r"(r[1]), "=r"(r[2]), "=r"(r[3]) : "r"(addr));
}
__device__ __forceinline__ void ldsm_x2t(uint32_t* r, const __half* p) {
    uint32_t addr = (uint32_t)__cvta_generic_to_shared(p);
    asm volatile("ldmatrix.sync.aligned.m8n8.x2.trans.shared.b16 {%0,%1}, [%2];"
                 : "=r"(r[0]), "=r"(r[1]) : "r"(addr));
}
__device__ __forceinline__ void mma16816(float* c, const uint32_t* a, const uint32_t* b) {
    asm volatile("mma.sync.aligned.m16n8k16.row.col.f32.f16.f16.f32 "
                 "{%0,%1,%2,%3}, {%4,%5,%6,%7}, {%8,%9}, {%0,%1,%2,%3};"
                 : "+f"(c[0]), "+f"(c[1]), "+f"(c[2]), "+f"(c[3])
                 : "r"(a[0]), "r"(a[1]), "r"(a[2]), "r"(a[3]), "r"(b[0]), "r"(b[1]));
}

#define LDA 72   // 64 + 8 halves pad
#define LDB 136  // 128 + 8 halves pad

__global__ __launch_bounds__(256)
void gemm_tc_kernel(const float* __restrict__ W,
                    const float* __restrict__ bias, int M) {
    __shared__ __half sA[128 * LDA];
    __shared__ __half sB[64 * LDB];
    __shared__ float sBias[128];

    const int t = threadIdx.x;
    const int wid = t >> 5, lane = t & 31;
    const int blockM = blockIdx.x * 128;
    const int warpM = (wid >> 1) * 32;
    const int warpN = (wid & 1) * 64;

    if (t < 128) sBias[t] = bias[t];

    float c[2][8][4];
#pragma unroll
    for (int mi = 0; mi < 2; mi++)
#pragma unroll
        for (int ni = 0; ni < 8; ni++)
#pragma unroll
            for (int q = 0; q < 4; q++) c[mi][ni][q] = 0.f;

#pragma unroll
    for (int stage = 0; stage < 2; stage++) {
        const int kOff = stage * 64;
#pragma unroll
        for (int l = 0; l < 4; l++) {
            int idx = (t + l * 256) * 8;
            int row = idx >> 6;
            int col = idx & 63;
            int grow = blockM + row;
            uint4 v = make_uint4(0u, 0u, 0u, 0u);
            if (grow < M)
                v = *(const uint4*)(g_xh + (size_t)grow * 128 + kOff + col);
            *(uint4*)(sA + row * LDA + col) = v;
        }
#pragma unroll
        for (int l = 0; l < 8; l++) {
            int idx = (t + l * 256) * 4;
            int row = idx >> 7;
            int col = idx & 127;
            float4 v = *(const float4*)(W + (size_t)(kOff + row) * 128 + col);
            __half2 h0 = __floats2half2_rn(v.x, v.y);
            __half2 h1 = __floats2half2_rn(v.z, v.w);
            uint2 pk;
            pk.x = *reinterpret_cast<unsigned*>(&h0);
            pk.y = *reinterpret_cast<unsigned*>(&h1);
            *(uint2*)(sB + row * LDB + col) = pk;
        }
        __syncthreads();

#pragma unroll
        for (int ks = 0; ks < 4; ks++) {
            const int kb = ks * 16;
            uint32_t a[2][4];
#pragma unroll
            for (int mi = 0; mi < 2; mi++) {
                int r = warpM + mi * 16 + (lane & 15);
                int cc = kb + ((lane >> 4) << 3);
                ldsm_x4(a[mi], sA + r * LDA + cc);
            }
#pragma unroll
            for (int ni = 0; ni < 8; ni++) {
                uint32_t b[2];
                int r = kb + (lane & 15);
                int cc = warpN + ni * 8;
                ldsm_x2t(b, sB + r * LDB + cc);
                mma16816(c[0][ni], a[0], b);
                mma16816(c[1][ni], a[1], b);
            }
        }
        __syncthreads();
    }

#pragma unroll
    for (int mi = 0; mi < 2; mi++) {
        int rBase = blockM + warpM + mi * 16 + (lane >> 2);
#pragma unroll
        for (int hh = 0; hh < 2; hh++) {
            int r = rBase + hh * 8;
            if (r < M) {
                float ds = g_dis[r];
#pragma unroll
                for (int ni = 0; ni < 8; ni++) {
                    int col = warpN + ni * 8 + (lane & 3) * 2;
                    float v0 = (c[mi][ni][hh * 2 + 0] + sBias[col]) * ds;
                    float v1 = (c[mi][ni][hh * 2 + 1] + sBias[col + 1]) * ds;
                    __half2 hv = __floats2half2_rn(v0, v1);
                    *(__half2*)(g_hbuf + (size_t)r * 128 + col) = hv;
                }
            }
        }
    }
}

// ======== CSR gather aggregation (fp16 rows, fp32 accumulate) ========
__device__ __forceinline__ void accum_row(float acc[4], const __half* rowp, int lane) {
    uint2 u = *(const uint2*)(rowp + lane * 4);
    __half2 h0 = *reinterpret_cast<__half2*>(&u.x);
    __half2 h1 = *reinterpret_cast<__half2*>(&u.y);
    float2 f0 = __half22float2(h0);
    float2 f1 = __half22float2(h1);
    acc[0] += f0.x; acc[1] += f0.y; acc[2] += f1.x; acc[3] += f1.y;
}

template <bool POOL>
__global__ __launch_bounds__(512)
void aggregate_kernel(int n, const int* __restrict__ batch,
                      const float* __restrict__ Wl) {
    int node = blockIdx.x * 16 + (threadIdx.x >> 5);
    if (node >= n) return;
    int lane = threadIdx.x & 31;
    const __half* __restrict__ h = g_hbuf;
    int s = g_rowptr[node];
    int e = g_rowptr[node + 1];
    float acc[4] = {0.f, 0.f, 0.f, 0.f};

    int p = s;
    for (; p + 8 <= e; p += 8) {      // 8 independent row gathers in flight
        int si[8];
#pragma unroll
        for (int q = 0; q < 8; q++) si[q] = g_csr[p + q];
#pragma unroll
        for (int q = 0; q < 8; q++)
            accum_row(acc, h + (size_t)si[q] * 128, lane);
    }
    if (p + 4 <= e) {
        int si[4];
#pragma unroll
        for (int q = 0; q < 4; q++) si[q] = g_csr[p + q];
#pragma unroll
        for (int q = 0; q < 4; q++)
            accum_row(acc, h + (size_t)si[q] * 128, lane);
        p += 4;
    }
    for (; p < e; p++)
        accum_row(acc, h + (size_t)g_csr[p] * 128, lane);

    float dd = g_dis[node];
#pragma unroll
    for (int j = 0; j < 4; j++) acc[j] = fmaxf(acc[j] * dd, 0.f);

    if (POOL) {
        float4 w = *(const float4*)(Wl + lane * 4);
        float sv = acc[0] * w.x + acc[1] * w.y + acc[2] * w.z + acc[3] * w.w;
#pragma unroll
        for (int o = 16; o > 0; o >>= 1) sv += __shfl_xor_sync(0xffffffffu, sv, o);
        if (lane == 0) {
            unsigned b = (unsigned)batch[node];
            if (b < NG) {
                atomicAdd(&g_gsum[b], sv);
                atomicAdd(&g_gcnt[b], 1.0f);
            }
        }
    } else {
        __half2 o0 = __floats2half2_rn(acc[0], acc[1]);
        __half2 o1 = __floats2half2_rn(acc[2], acc[3]);
        uint2 pk;
        pk.x = *reinterpret_cast<unsigned*>(&o0);
        pk.y = *reinterpret_cast<unsigned*>(&o1);
        *(uint2*)(g_xh + (size_t)node * 128 + lane * 4) = pk;
        // restore the zero-state invariant for the next call (deg/tmp are
        // no longer needed this call; this runs in layer-1 & layer-2,
        // second zeroing is idempotent)
        if (lane == 0) { g_deg[node] = 0; g_tmp[node] = 0; }
    }
}

__global__ void final_kernel(float* __restrict__ out, const float* __restrict__ bl) {
    int g = threadIdx.x;
    if (g < NG) {
        out[g] = g_gsum[g] / fmaxf(g_gcnt[g], 1.0f) + bl[0];
        g_gsum[g] = 0.f;    // restore zero-state for next call
        g_gcnt[g] = 0.f;
    }
}

// --------------------------------------------------------------------------
extern "C" void kernel_launch(void* const* d_in, const int* in_sizes, int n_in,
                              void* d_out, int out_size) {
    const float* x     = (const float*)d_in[0];
    const int*   eidx  = (const int*)d_in[1];
    const int*   batch = (const int*)d_in[2];

    int wbase = (in_sizes[3] < 128) ? 4 : 3;
    const float* W1 = (const float*)d_in[wbase + 0];
    const float* b1 = (const float*)d_in[wbase + 1];
    const float* W2 = (const float*)d_in[wbase + 2];
    const float* b2 = (const float*)d_in[wbase + 3];
    const float* W3 = (const float*)d_in[wbase + 4];
    const float* b3 = (const float*)d_in[wbase + 5];
    const float* Wl = (const float*)d_in[wbase + 6];
    const float* bl = (const float*)d_in[wbase + 7];
    float* out = (float*)d_out;

    const int N = in_sizes[0] / F;          // 40000
    const int E = in_sizes[1] / 2;          // 640000
    const int* erow = eidx;
    const int* ecol = eidx + E;
    const int NB = (N + SCAN_TILE - 1) / SCAN_TILE;

    const int T = 256;
    convertx_kernel<<<(N * F / 4 + T - 1) / T, T>>>(x, N * F / 4);
    count_kernel<<<((E + 1) / 2 + T - 1) / T, T>>>(ecol, E, N);
    scan_phaseA<<<NB, SCAN_TILE>>>(N);
    scan_phaseC<<<NB, SCAN_TILE>>>(N, NB);
    scatter_kernel<<<((E + N + 1) / 2 + T - 1) / T, T>>>(erow, ecol, E, N);

    const int gemmBlocks = (N + 127) / 128;
    const int aggBlocks  = (N + 15) / 16;

    // layer 1
    gemm_tc_kernel<<<gemmBlocks, 256>>>(W1, b1, N);
    aggregate_kernel<false><<<aggBlocks, 512>>>(N, batch, Wl);
    // layer 2
    gemm_tc_kernel<<<gemmBlocks, 256>>>(W2, b2, N);
    aggregate_kernel<false><<<aggBlocks, 512>>>(N, batch, Wl);
    // layer 3 (+ fused global mean pool)
    gemm_tc_kernel<<<gemmBlocks, 256>>>(W3, b3, N);
    aggregate_kernel<true><<<aggBlocks, 512>>>(N, batch, Wl);

    final_kernel<<<1, 64>>>(out, bl);
}

// round 10
// speedup vs baseline: 2.0426x; 1.0315x over previous
#include <cuda_runtime.h>
#include <cuda_fp16.h>
#include <stdint.h>

// Problem constants
#define MAXN 40000
#define MAXE 640000
#define NG   64
#define F    128
#define SCAN_TILE 1024
#define MAXNB ((MAXN + SCAN_TILE - 1) / SCAN_TILE)   // 40

// ---------------- device scratch (zero at load; each call restores zeros) --
__device__ __half g_xh[(size_t)MAXN * F];    // fp16 ping: x converted / agg output
__device__ __half g_hbuf[(size_t)MAXN * F];  // fp16 pong: GEMM output (prescaled)
__device__ int    g_deg[MAXN];               // edge-count only; MUST be 0 at entry
__device__ float  g_dis[MAXN];
__device__ int    g_rowptr[MAXN + 1];
__device__ int    g_tmp[MAXN];               // MUST be 0 at entry
__device__ int    g_csr[MAXE];
__device__ int    g_blocksums[MAXNB];
__device__ float  g_gsum[NG];                // MUST be 0 at entry
__device__ float  g_gcnt[NG];                // MUST be 0 at entry

// -------- PDL intrinsics (no-ops when launched without the attribute) -----
__device__ __forceinline__ void gdc_launch() {
    asm volatile("griddepcontrol.launch_dependents;");
}
__device__ __forceinline__ void gdc_wait() {
    asm volatile("griddepcontrol.wait;" ::: "memory");
}

// -------- fused: convert x -> fp16  AND  degree histogram ----------------
// blocks [0, cBlocks): conversion; blocks [cBlocks, ...): edge counting
__global__ void prep_kernel(const float* __restrict__ x, int total4,
                            const int* __restrict__ col, int E, int n,
                            int cBlocks) {
    gdc_launch();
    if (blockIdx.x < cBlocks) {
        int i = blockIdx.x * blockDim.x + threadIdx.x;
        if (i < total4) {
            float4 v = *(const float4*)(x + (size_t)i * 4);
            __half2 h0 = __floats2half2_rn(v.x, v.y);
            __half2 h1 = __floats2half2_rn(v.z, v.w);
            uint2 pk;
            pk.x = *reinterpret_cast<unsigned*>(&h0);
            pk.y = *reinterpret_cast<unsigned*>(&h1);
            *(uint2*)(g_xh + (size_t)i * 4) = pk;
        }
    } else {
        int i = (blockIdx.x - cBlocks) * blockDim.x + threadIdx.x;
        int e = i * 2;
        if (e + 1 < E) {
            int2 c2 = *(const int2*)(col + e);
            if ((unsigned)c2.x < (unsigned)n) atomicAdd(&g_deg[c2.x], 1);
            if ((unsigned)c2.y < (unsigned)n) atomicAdd(&g_deg[c2.y], 1);
        } else if (e < E) {
            unsigned c = (unsigned)col[e];
            if (c < (unsigned)n) atomicAdd(&g_deg[c], 1);
        }
    }
}

// -------- scan phase A: block sums of (deg+1) + dis = rsqrt(deg+1) --------
__global__ __launch_bounds__(SCAN_TILE)
void scan_phaseA(int n) {
    gdc_launch();
    gdc_wait();
    __shared__ int sh[32];
    int tid = threadIdx.x, lane = tid & 31, wid = tid >> 5;
    int i = blockIdx.x * SCAN_TILE + tid;
    int v = (i < n) ? (g_deg[i] + 1) : 0;   // +1 = self loop (not in CSR)
    if (i < n) g_dis[i] = rsqrtf((float)v);
    int x = v;
#pragma unroll
    for (int o = 16; o > 0; o >>= 1) x += __shfl_xor_sync(0xffffffffu, x, o);
    if (lane == 0) sh[wid] = x;
    __syncthreads();
    if (wid == 0) {
        int w = sh[lane];
#pragma unroll
        for (int o = 16; o > 0; o >>= 1) w += __shfl_xor_sync(0xffffffffu, w, o);
        if (lane == 0) g_blocksums[blockIdx.x] = w;
    }
}

// -------- scan phase C: rowptr over edge counts only (exclude self loops) -
// rowptr built from deg (without +1): CSR holds edges only.
__global__ __launch_bounds__(SCAN_TILE)
void scan_phaseC(int n, int nb) {
    gdc_launch();
    gdc_wait();
    __shared__ int sh[32];
    __shared__ int bexcl[64];
    __shared__ int w0tot;
    int tid = threadIdx.x, lane = tid & 31, wid = tid >> 5;

    if (tid < 64) {
        // blocksums counted (deg+1); subtract the tile's node count to get edges-only
        int tileN = 0;
        if (tid < nb) {
            int lo = tid * SCAN_TILE;
            int hi = lo + SCAN_TILE; if (hi > n) hi = n;
            tileN = hi - lo;
        }
        int v = (tid < nb) ? (g_blocksums[tid] - tileN) : 0;
        int x = v;
#pragma unroll
        for (int o = 1; o < 32; o <<= 1) {
            int y = __shfl_up_sync(0xffffffffu, x, o);
            if (lane >= o) x += y;
        }
        if (tid == 31) w0tot = x;
        bexcl[tid] = x - v;
    }
    __syncthreads();
    if (tid >= 32 && tid < 64) bexcl[tid] += w0tot;
    __syncthreads();
    int blockOff = bexcl[blockIdx.x];
    if (tid == 0 && blockIdx.x == 0) {
        int lastTileN = n - (nb - 1) * SCAN_TILE;
        g_rowptr[n] = bexcl[nb - 1] + g_blocksums[nb - 1] - lastTileN;
    }

    int i = blockIdx.x * SCAN_TILE + tid;
    int v = (i < n) ? g_deg[i] : 0;       // edges only
    int x = v;
#pragma unroll
    for (int o = 1; o < 32; o <<= 1) {
        int y = __shfl_up_sync(0xffffffffu, x, o);
        if (lane >= o) x += y;
    }
    if (lane == 31) sh[wid] = x;
    __syncthreads();
    if (wid == 0) {
        int w = sh[lane];
#pragma unroll
        for (int o = 1; o < 32; o <<= 1) {
            int y = __shfl_up_sync(0xffffffffu, w, o);
            if (lane >= o) w += y;
        }
        sh[lane] = w;
    }
    __syncthreads();
    int woff = (wid > 0) ? sh[wid - 1] : 0;
    if (i < n) g_rowptr[i] = blockOff + woff + x - v;
}

// -------- scatter edges into CSR (edges only), 2 per thread ---------------
__global__ void scatter_kernel(const int* __restrict__ row,
                               const int* __restrict__ col,
                               int E, int n) {
    gdc_launch();
    gdc_wait();
    int i = blockIdx.x * blockDim.x + threadIdx.x;
#pragma unroll
    for (int q = 0; q < 2; q++) {
        int idx = i * 2 + q;
        if (idx >= E) return;
        unsigned d = (unsigned)col[idx];
        unsigned s = (unsigned)row[idx];
        if (d >= (unsigned)n || s >= (unsigned)n) continue;
        int p = g_rowptr[d] + atomicAdd(&g_tmp[d], 1);
        g_csr[p] = (int)s;
    }
}

// ======== Tensor-core GEMM: g_hbuf = half( dis * (g_xh @ W + bias) ) ========
__device__ __forceinline__ void ldsm_x4(uint32_t* r, const __half* p) {
    uint32_t addr = (uint32_t)__cvta_generic_to_shared(p);
    asm volatile("ldmatrix.sync.aligned.m8n8.x4.shared.b16 {%0,%1,%2,%3}, [%4];"
                 : "=r"(r[0]), "=r"(r[1]), "=r"(r[2]), "=r"(r[3]) : "r"(addr));
}
__device__ __forceinline__ void ldsm_x2t(uint32_t* r, const __half* p) {
    uint32_t addr = (uint32_t)__cvta_generic_to_shared(p);
    asm volatile("ldmatrix.sync.aligned.m8n8.x2.trans.shared.b16 {%0,%1}, [%2];"
                 : "=r"(r[0]), "=r"(r[1]) : "r"(addr));
}
__device__ __forceinline__ void mma16816(float* c, const uint32_t* a, const uint32_t* b) {
    asm volatile("mma.sync.aligned.m16n8k16.row.col.f32.f16.f16.f32 "
                 "{%0,%1,%2,%3}, {%4,%5,%6,%7}, {%8,%9}, {%0,%1,%2,%3};"
                 : "+f"(c[0]), "+f"(c[1]), "+f"(c[2]), "+f"(c[3])
                 : "r"(a[0]), "r"(a[1]), "r"(a[2]), "r"(a[3]), "r"(b[0]), "r"(b[1]));
}

#define LDA 72   // 64 + 8 halves pad
#define LDB 136  // 128 + 8 halves pad

__global__ __launch_bounds__(256)
void gemm_tc_kernel(const float* __restrict__ W,
                    const float* __restrict__ bias, int M) {
    __shared__ __half sA[128 * LDA];
    __shared__ __half sB[64 * LDB];
    __shared__ float sBias[128];

    gdc_launch();
    const int t = threadIdx.x;
    const int wid = t >> 5, lane = t & 31;
    const int blockM = blockIdx.x * 128;
    const int warpM = (wid >> 1) * 32;
    const int warpN = (wid & 1) * 64;

    if (t < 128) sBias[t] = bias[t];   // external input: safe pre-wait

    float c[2][8][4];
#pragma unroll
    for (int mi = 0; mi < 2; mi++)
#pragma unroll
        for (int ni = 0; ni < 8; ni++)
#pragma unroll
            for (int q = 0; q < 4; q++) c[mi][ni][q] = 0.f;

    gdc_wait();   // before reading g_xh / g_dis

#pragma unroll
    for (int stage = 0; stage < 2; stage++) {
        const int kOff = stage * 64;
#pragma unroll
        for (int l = 0; l < 4; l++) {
            int idx = (t + l * 256) * 8;
            int row = idx >> 6;
            int col = idx & 63;
            int grow = blockM + row;
            uint4 v = make_uint4(0u, 0u, 0u, 0u);
            if (grow < M)
                v = *(const uint4*)(g_xh + (size_t)grow * 128 + kOff + col);
            *(uint4*)(sA + row * LDA + col) = v;
        }
#pragma unroll
        for (int l = 0; l < 8; l++) {
            int idx = (t + l * 256) * 4;
            int row = idx >> 7;
            int col = idx & 127;
            float4 v = *(const float4*)(W + (size_t)(kOff + row) * 128 + col);
            __half2 h0 = __floats2half2_rn(v.x, v.y);
            __half2 h1 = __floats2half2_rn(v.z, v.w);
            uint2 pk;
            pk.x = *reinterpret_cast<unsigned*>(&h0);
            pk.y = *reinterpret_cast<unsigned*>(&h1);
            *(uint2*)(sB + row * LDB + col) = pk;
        }
        __syncthreads();

#pragma unroll
        for (int ks = 0; ks < 4; ks++) {
            const int kb = ks * 16;
            uint32_t a[2][4];
#pragma unroll
            for (int mi = 0; mi < 2; mi++) {
                int r = warpM + mi * 16 + (lane & 15);
                int cc = kb + ((lane >> 4) << 3);
                ldsm_x4(a[mi], sA + r * LDA + cc);
            }
#pragma unroll
            for (int ni = 0; ni < 8; ni++) {
                uint32_t b[2];
                int r = kb + (lane & 15);
                int cc = warpN + ni * 8;
                ldsm_x2t(b, sB + r * LDB + cc);
                mma16816(c[0][ni], a[0], b);
                mma16816(c[1][ni], a[1], b);
            }
        }
        __syncthreads();
    }

#pragma unroll
    for (int mi = 0; mi < 2; mi++) {
        int rBase = blockM + warpM + mi * 16 + (lane >> 2);
#pragma unroll
        for (int hh = 0; hh < 2; hh++) {
            int r = rBase + hh * 8;
            if (r < M) {
                float ds = g_dis[r];
#pragma unroll
                for (int ni = 0; ni < 8; ni++) {
                    int col = warpN + ni * 8 + (lane & 3) * 2;
                    float v0 = (c[mi][ni][hh * 2 + 0] + sBias[col]) * ds;
                    float v1 = (c[mi][ni][hh * 2 + 1] + sBias[col + 1]) * ds;
                    __half2 hv = __floats2half2_rn(v0, v1);
                    *(__half2*)(g_hbuf + (size_t)r * 128 + col) = hv;
                }
            }
        }
    }
}

// ======== CSR gather aggregation (fp16 rows, fp32 accumulate) ========
__device__ __forceinline__ void accum_row(float acc[4], const __half* rowp, int lane) {
    uint2 u = *(const uint2*)(rowp + lane * 4);
    __half2 h0 = *reinterpret_cast<__half2*>(&u.x);
    __half2 h1 = *reinterpret_cast<__half2*>(&u.y);
    float2 f0 = __half22float2(h0);
    float2 f1 = __half22float2(h1);
    acc[0] += f0.x; acc[1] += f0.y; acc[2] += f1.x; acc[3] += f1.y;
}

template <bool POOL>
__global__ __launch_bounds__(512)
void aggregate_kernel(int n, const int* __restrict__ batch,
                      const float* __restrict__ Wl) {
    gdc_launch();
    gdc_wait();
    int node = blockIdx.x * 16 + (threadIdx.x >> 5);
    if (node >= n) return;
    int lane = threadIdx.x & 31;
    const __half* __restrict__ h = g_hbuf;
    int s = g_rowptr[node];
    int e = g_rowptr[node + 1];
    float acc[4] = {0.f, 0.f, 0.f, 0.f};

    accum_row(acc, h + (size_t)node * 128, lane);   // self loop

    int p = s;
    for (; p + 4 <= e; p += 4) {
        int si[4];
#pragma unroll
        for (int q = 0; q < 4; q++) si[q] = g_csr[p + q];
#pragma unroll
        for (int q = 0; q < 4; q++)
            accum_row(acc, h + (size_t)si[q] * 128, lane);
    }
    for (; p < e; p++)
        accum_row(acc, h + (size_t)g_csr[p] * 128, lane);

    float dd = g_dis[node];
#pragma unroll
    for (int j = 0; j < 4; j++) acc[j] = fmaxf(acc[j] * dd, 0.f);

    if (POOL) {
        float4 w = *(const float4*)(Wl + lane * 4);
        float sv = acc[0] * w.x + acc[1] * w.y + acc[2] * w.z + acc[3] * w.w;
#pragma unroll
        for (int o = 16; o > 0; o >>= 1) sv += __shfl_xor_sync(0xffffffffu, sv, o);
        if (lane == 0) {
            unsigned b = (unsigned)batch[node];
            if (b < NG) {
                atomicAdd(&g_gsum[b], sv);
                atomicAdd(&g_gcnt[b], 1.0f);
            }
        }
    } else {
        __half2 o0 = __floats2half2_rn(acc[0], acc[1]);
        __half2 o1 = __floats2half2_rn(acc[2], acc[3]);
        uint2 pk;
        pk.x = *reinterpret_cast<unsigned*>(&o0);
        pk.y = *reinterpret_cast<unsigned*>(&o1);
        *(uint2*)(g_xh + (size_t)node * 128 + lane * 4) = pk;
        // restore zero-state for next call (idempotent across layers 1,2)
        if (lane == 0) { g_deg[node] = 0; g_tmp[node] = 0; }
    }
}

__global__ void final_kernel(float* __restrict__ out, const float* __restrict__ bl) {
    gdc_wait();
    int g = threadIdx.x;
    if (g < NG) {
        out[g] = g_gsum[g] / fmaxf(g_gcnt[g], 1.0f) + bl[0];
        g_gsum[g] = 0.f;
        g_gcnt[g] = 0.f;
    }
}

// --------------------------------------------------------------------------
template <typename... Args>
static void launch_pdl(void (*kern)(Args...), dim3 grid, dim3 block,
                       Args... args) {
    cudaLaunchConfig_t cfg = {};
    cfg.gridDim = grid;
    cfg.blockDim = block;
    cudaLaunchAttribute attr[1];
    attr[0].id = cudaLaunchAttributeProgrammaticStreamSerialization;
    attr[0].val.programmaticStreamSerializationAllowed = 1;
    cfg.attrs = attr;
    cfg.numAttrs = 1;
    cudaLaunchKernelEx(&cfg, kern, args...);
}

extern "C" void kernel_launch(void* const* d_in, const int* in_sizes, int n_in,
                              void* d_out, int out_size) {
    const float* x     = (const float*)d_in[0];
    const int*   eidx  = (const int*)d_in[1];
    const int*   batch = (const int*)d_in[2];

    int wbase = (in_sizes[3] < 128) ? 4 : 3;
    const float* W1 = (const float*)d_in[wbase + 0];
    const float* b1 = (const float*)d_in[wbase + 1];
    const float* W2 = (const float*)d_in[wbase + 2];
    const float* b2 = (const float*)d_in[wbase + 3];
    const float* W3 = (const float*)d_in[wbase + 4];
    const float* b3 = (const float*)d_in[wbase + 5];
    const float* Wl = (const float*)d_in[wbase + 6];
    const float* bl = (const float*)d_in[wbase + 7];
    float* out = (float*)d_out;

    const int N = in_sizes[0] / F;          // 40000
    const int E = in_sizes[1] / 2;          // 640000
    const int* erow = eidx;
    const int* ecol = eidx + E;
    const int NB = (N + SCAN_TILE - 1) / SCAN_TILE;

    const int T = 256;
    const int total4  = N * F / 4;
    const int cBlocks = (total4 + T - 1) / T;
    const int eBlocks = ((E + 1) / 2 + T - 1) / T;

    // first node: plain launch
    prep_kernel<<<cBlocks + eBlocks, T>>>(x, total4, ecol, E, N, cBlocks);

    launch_pdl(scan_phaseA, dim3(NB), dim3(SCAN_TILE), N);
    launch_pdl(scan_phaseC, dim3(NB), dim3(SCAN_TILE), N, NB);
    launch_pdl(scatter_kernel, dim3(eBlocks), dim3(T), erow, ecol, E, N);

    const int gemmBlocks = (N + 127) / 128;
    const int aggBlocks  = (N + 15) / 16;

    launch_pdl(gemm_tc_kernel, dim3(gemmBlocks), dim3(256), W1, b1, N);
    launch_pdl(aggregate_kernel<false>, dim3(aggBlocks), dim3(512), N, batch, Wl);
    launch_pdl(gemm_tc_kernel, dim3(gemmBlocks), dim3(256), W2, b2, N);
    launch_pdl(aggregate_kernel<false>, dim3(aggBlocks), dim3(512), N, batch, Wl);
    launch_pdl(gemm_tc_kernel, dim3(gemmBlocks), dim3(256), W3, b3, N);
    launch_pdl(aggregate_kernel<true>, dim3(aggBlocks), dim3(512), N, batch, Wl);

    launch_pdl(final_kernel, dim3(1), dim3(64), out, (const float*)bl);
}